// round 2
// baseline (speedup 1.0000x reference)
#include <cuda_runtime.h>
#include <cstdint>

// DecoderLSTM: batch dimension is degenerate (features unused, x0=0, shared
// weights) -> compute ONE 84-step 2-layer LSTM (H=512) cooperatively across
// 128 persistent CTAs, then broadcast points[84][3] into out[16384][84][3]
// masked by seq_lengths.

#define NCTA   128
#define NT     256
#define HDIM   512
#define TSTEPS 84
#define BROWS  128        // batch rows per CTA (16384/128)

// Cross-CTA exchange state. Flags are monotonic counters (never reset): each
// run reads its own flag at entry as the epoch base, so graph replays are
// deterministic. Padded to one 128B line per CTA to avoid LTS hotspots.
__device__ __align__(16) float    g_h0[2][HDIM];
__device__ __align__(16) float    g_h1[2][HDIM];
__device__ unsigned g_flags[NCTA][32];

__device__ __forceinline__ unsigned ldacq(const unsigned* p) {
    unsigned v;
    asm volatile("ld.acquire.gpu.u32 %0, [%1];" : "=r"(v) : "l"(p) : "memory");
    return v;
}
__device__ __forceinline__ void strel(unsigned* p, unsigned v) {
    asm volatile("st.release.gpu.u32 [%0], %1;" :: "l"(p), "r"(v) : "memory");
}
__device__ __forceinline__ float sigm(float z)  { return 1.0f / (1.0f + __expf(-z)); }
__device__ __forceinline__ float tanh_(float z) { return 2.0f / (1.0f + __expf(-2.0f * z)) - 1.0f; }

__global__ void __launch_bounds__(NT, 1)
lstm_persistent_kernel(const int* __restrict__ seq,
                       const float* __restrict__ Wih0, const float* __restrict__ Whh0,
                       const float* __restrict__ bih0, const float* __restrict__ bhh0,
                       const float* __restrict__ Wih1, const float* __restrict__ Whh1,
                       const float* __restrict__ bih1, const float* __restrict__ bhh1,
                       const float* __restrict__ Wpc,  const float* __restrict__ bpc,
                       float* __restrict__ out)
{
    __shared__ float sh0[HDIM];       // h0(t-1), then h0(t) after stage
    __shared__ float sh1[HDIM];       // h1(t-1), then h1(t) after stage
    __shared__ float Wpcs[3 * HDIM];
    __shared__ float pts[TSTEPS * 3];
    __shared__ float wx0s[16 * 3];    // W_ih0 rows owned by this CTA
    __shared__ float bias0[16], bias1[16];
    __shared__ float zbuf[16];        // reduced gate pre-activations
    __shared__ float hpost[4];        // h slice to post
    __shared__ float bpcs[3];

    const int tid  = threadIdx.x;
    const int w    = tid >> 5;
    const int lane = tid & 31;
    const int cta  = blockIdx.x;

    // ---- load owned weight rows into registers ----
    // 16 gate-rows per layer per CTA: local row lr = g*4 + u, global row
    // grow = g*512 + 4*cta + u. Warp w owns lr = {2w, 2w+1}.
    float whh0[2][16], whh1[2][16], wih1[2][16];
    #pragma unroll
    for (int r = 0; r < 2; r++) {
        int lr = 2 * w + r;
        int g = lr >> 2, u = lr & 3;
        size_t grow = (size_t)(g * HDIM + cta * 4 + u);
        const float* p0 = Whh0 + grow * HDIM + lane;
        const float* p1 = Whh1 + grow * HDIM + lane;
        const float* p2 = Wih1 + grow * HDIM + lane;
        #pragma unroll
        for (int m = 0; m < 16; m++) {
            whh0[r][m] = p0[m * 32];
            whh1[r][m] = p1[m * 32];
            wih1[r][m] = p2[m * 32];
        }
    }
    for (int i = tid; i < 3 * HDIM; i += NT) Wpcs[i] = Wpc[i];
    if (tid < 48) {
        int lr = tid / 3, c = tid - 3 * lr;
        int g = lr >> 2, u = lr & 3;
        wx0s[tid] = Wih0[(g * HDIM + cta * 4 + u) * 3 + c];
    }
    if (tid < 16) {
        int g = tid >> 2, u = tid & 3;
        int grow = g * HDIM + cta * 4 + u;
        bias0[tid] = bih0[grow] + bhh0[grow];
        bias1[tid] = bih1[grow] + bhh1[grow];
    }
    if (tid < 3) bpcs[tid] = bpc[tid];
    for (int i = tid; i < HDIM; i += NT) { sh0[i] = 0.0f; sh1[i] = 0.0f; }

    // Epoch base: all flags are equal at kernel entry (each run increments
    // every flag by exactly 2*TSTEPS).
    unsigned basePoll = 0;
    if (tid < NCTA) basePoll = ldacq(&g_flags[tid][0]);
    const unsigned baseOwn = __shfl_sync(0xffffffffu, basePoll, 0);  // value identical anyway

    float c0 = 0.0f, c1 = 0.0f;   // cell state, live in threads tid<4
    __syncthreads();

    for (int t = 0; t < TSTEPS; t++) {
        const int par = t & 1;
        // ================= layer 0 =================
        float a0 = 0.0f, a1 = 0.0f;
        #pragma unroll
        for (int m = 0; m < 16; m++) {
            float h = sh0[lane + 32 * m];
            a0 += whh0[0][m] * h;
            a1 += whh0[1][m] * h;
        }
        #pragma unroll
        for (int o = 16; o; o >>= 1) {
            a0 += __shfl_xor_sync(0xffffffffu, a0, o);
            a1 += __shfl_xor_sync(0xffffffffu, a1, o);
        }
        if (lane == 0) { zbuf[2 * w] = a0; zbuf[2 * w + 1] = a1; }
        __syncthreads();
        if (tid < 4) {
            float x0 = 0.0f, x1 = 0.0f, x2 = 0.0f;
            if (t > 0) { x0 = pts[3*(t-1)]; x1 = pts[3*(t-1)+1]; x2 = pts[3*(t-1)+2]; }
            int u = tid;
            float zi = zbuf[ 0+u] + bias0[ 0+u] + wx0s[( 0+u)*3]*x0 + wx0s[( 0+u)*3+1]*x1 + wx0s[( 0+u)*3+2]*x2;
            float zf = zbuf[ 4+u] + bias0[ 4+u] + wx0s[( 4+u)*3]*x0 + wx0s[( 4+u)*3+1]*x1 + wx0s[( 4+u)*3+2]*x2;
            float zg = zbuf[ 8+u] + bias0[ 8+u] + wx0s[( 8+u)*3]*x0 + wx0s[( 8+u)*3+1]*x1 + wx0s[( 8+u)*3+2]*x2;
            float zo = zbuf[12+u] + bias0[12+u] + wx0s[(12+u)*3]*x0 + wx0s[(12+u)*3+1]*x1 + wx0s[(12+u)*3+2]*x2;
            c0 = sigm(zf) * c0 + sigm(zi) * tanh_(zg);
            hpost[u] = sigm(zo) * tanh_(c0);
        }
        __syncthreads();
        if (tid == 0) {
            float4 hv = make_float4(hpost[0], hpost[1], hpost[2], hpost[3]);
            __stcg(reinterpret_cast<float4*>(&g_h0[par][cta * 4]), hv);
            strel(&g_flags[cta][0], baseOwn + (unsigned)(2 * t + 1));
        }
        if (tid < NCTA) {
            const unsigned tgt = basePoll + (unsigned)(2 * t + 1);
            while ((int)(ldacq(&g_flags[tid][0]) - tgt) < 0) { }
        }
        __syncthreads();
        for (int i = tid; i < HDIM; i += NT) sh0[i] = __ldcg(&g_h0[par][i]);
        __syncthreads();

        // ================= layer 1 =================
        float b0 = 0.0f, b1 = 0.0f;
        #pragma unroll
        for (int m = 0; m < 16; m++) {
            float hp = sh1[lane + 32 * m];
            float hn = sh0[lane + 32 * m];
            b0 += whh1[0][m] * hp + wih1[0][m] * hn;
            b1 += whh1[1][m] * hp + wih1[1][m] * hn;
        }
        #pragma unroll
        for (int o = 16; o; o >>= 1) {
            b0 += __shfl_xor_sync(0xffffffffu, b0, o);
            b1 += __shfl_xor_sync(0xffffffffu, b1, o);
        }
        if (lane == 0) { zbuf[2 * w] = b0; zbuf[2 * w + 1] = b1; }
        __syncthreads();
        if (tid < 4) {
            int u = tid;
            float zi = zbuf[ 0+u] + bias1[ 0+u];
            float zf = zbuf[ 4+u] + bias1[ 4+u];
            float zg = zbuf[ 8+u] + bias1[ 8+u];
            float zo = zbuf[12+u] + bias1[12+u];
            c1 = sigm(zf) * c1 + sigm(zi) * tanh_(zg);
            hpost[u] = sigm(zo) * tanh_(c1);
        }
        __syncthreads();
        if (tid == 0) {
            float4 hv = make_float4(hpost[0], hpost[1], hpost[2], hpost[3]);
            __stcg(reinterpret_cast<float4*>(&g_h1[par][cta * 4]), hv);
            strel(&g_flags[cta][0], baseOwn + (unsigned)(2 * t + 2));
        }
        if (tid < NCTA) {
            const unsigned tgt = basePoll + (unsigned)(2 * t + 2);
            while ((int)(ldacq(&g_flags[tid][0]) - tgt) < 0) { }
        }
        __syncthreads();
        for (int i = tid; i < HDIM; i += NT) sh1[i] = __ldcg(&g_h1[par][i]);
        __syncthreads();

        // ================= output projection (every CTA, locally) ==========
        if (w < 3) {
            float s = 0.0f;
            #pragma unroll
            for (int m = 0; m < 16; m++)
                s += Wpcs[w * HDIM + lane + 32 * m] * sh1[lane + 32 * m];
            #pragma unroll
            for (int o = 16; o; o >>= 1) s += __shfl_xor_sync(0xffffffffu, s, o);
            if (lane == 0) pts[3 * t + w] = s + bpcs[w];
        }
        __syncthreads();   // pts[t] ready for next step's x and final write
    }

    // ---- broadcast: out[row][t][j] = (t < seq[row]) ? pts[t][j] : 0 ----
    // Each CTA owns 128 contiguous batch rows; 63 float4 per row (252 floats).
    const int row0 = cta * BROWS;
    for (int idx = tid; idx < BROWS * 63; idx += NT) {
        int rl = idx / 63;
        int q  = idx - 63 * rl;
        int row = row0 + rl;
        int L = seq[row];
        int e = 4 * q;
        float4 v;
        v.x = ((e    ) / 3 < L) ? pts[e    ] : 0.0f;
        v.y = ((e + 1) / 3 < L) ? pts[e + 1] : 0.0f;
        v.z = ((e + 2) / 3 < L) ? pts[e + 2] : 0.0f;
        v.w = ((e + 3) / 3 < L) ? pts[e + 3] : 0.0f;
        reinterpret_cast<float4*>(out)[(size_t)row * 63 + q] = v;
    }
}

extern "C" void kernel_launch(void* const* d_in, const int* in_sizes, int n_in,
                              void* d_out, int out_size)
{
    // metadata order: 0 features (unused), 1 seq_lengths, 2 W_ih0, 3 W_hh0,
    // 4 b_ih0, 5 b_hh0, 6 W_ih1, 7 W_hh1, 8 b_ih1, 9 b_hh1, 10 W_pc, 11 b_pc
    (void)in_sizes; (void)n_in; (void)out_size;
    lstm_persistent_kernel<<<NCTA, NT>>>(
        (const int*)  d_in[1],
        (const float*)d_in[2], (const float*)d_in[3],
        (const float*)d_in[4], (const float*)d_in[5],
        (const float*)d_in[6], (const float*)d_in[7],
        (const float*)d_in[8], (const float*)d_in[9],
        (const float*)d_in[10], (const float*)d_in[11],
        (float*)d_out);
}

// round 3
// speedup vs baseline: 1.0389x; 1.0389x over previous
#include <cuda_runtime.h>
#include <cstdint>

// DecoderLSTM on B200: batch dimension is degenerate (features unused, x0=0,
// shared weights) -> ONE 84-step 2-layer LSTM (H=512) computed cooperatively
// by 128 persistent CTAs with single-L2-trip tagged-word exchanges, then a
// masked broadcast of points[84][3] into out[16384][84][3].

#define NCTA   128
#define NT     256
#define HDIM   512
#define TSTEPS 84
#define BROWS  128     // batch rows per CTA

typedef unsigned long long u64t;
typedef unsigned int u32t;

// Tagged posts: upper 32 = monotonic version tag, lower 32 = float bits.
// 8B-aligned relaxed accesses are single-copy atomic -> tag+payload travel
// together; no separate flag/acquire round needed. Never reset: each run
// reads its own CTA's words at entry as the tag base (all words are equal
// between runs by construction), so CUDA-graph replays are deterministic.
__device__ u64t g_P0[2][HDIM];   // layer-0 h posts, double-buffered by parity
__device__ u64t g_P1[2][HDIM];   // layer-1 h posts

static __device__ __forceinline__ void post64(u64t* p, u32t tag, float h) {
    u64t v = ((u64t)tag << 32) | (u64t)__float_as_uint(h);
    asm volatile("st.relaxed.gpu.global.u64 [%0], %1;" :: "l"(p), "l"(v) : "memory");
}
static __device__ __forceinline__ u64t ldrel(const u64t* p) {
    u64t v;
    asm volatile("ld.relaxed.gpu.global.u64 %0, [%1];" : "=l"(v) : "l"(p) : "memory");
    return v;
}
__device__ __forceinline__ float sigm(float z)  { return 1.0f / (1.0f + __expf(-z)); }
__device__ __forceinline__ float tanh_(float z) { return 2.0f / (1.0f + __expf(-2.0f * z)) - 1.0f; }

#define BARS(id, n) asm volatile("bar.sync %0, %1;" :: "r"(id), "r"(n) : "memory")

// Poll 4 tagged words (warp-coalesced stride-128 layout), stage floats to smem.
static __device__ __forceinline__ void poll4(const u64t* arr, int k, u32t tag, float* dst) {
    u64t v0 = ldrel(arr + k);
    u64t v1 = ldrel(arr + k + 128);
    u64t v2 = ldrel(arr + k + 256);
    u64t v3 = ldrel(arr + k + 384);
    while ((u32t)(v0 >> 32) != tag) v0 = ldrel(arr + k);
    while ((u32t)(v1 >> 32) != tag) v1 = ldrel(arr + k + 128);
    while ((u32t)(v2 >> 32) != tag) v2 = ldrel(arr + k + 256);
    while ((u32t)(v3 >> 32) != tag) v3 = ldrel(arr + k + 384);
    dst[k]       = __uint_as_float((u32t)v0);
    dst[k + 128] = __uint_as_float((u32t)v1);
    dst[k + 256] = __uint_as_float((u32t)v2);
    dst[k + 384] = __uint_as_float((u32t)v3);
}

__global__ void __launch_bounds__(NT, 1)
lstm_persistent_kernel(const int* __restrict__ seq,
                       const float* __restrict__ Wih0, const float* __restrict__ Whh0,
                       const float* __restrict__ bih0, const float* __restrict__ bhh0,
                       const float* __restrict__ Wih1, const float* __restrict__ Whh1,
                       const float* __restrict__ bih1, const float* __restrict__ bhh1,
                       const float* __restrict__ Wpc,  const float* __restrict__ bpc,
                       float* __restrict__ out)
{
    __shared__ float h0s[2][HDIM];
    __shared__ float h1s[2][HDIM];
    __shared__ float pts[TSTEPS * 3];
    __shared__ u32t  sbase[4];      // tag bases: P0 par0/par1, P1 par0/par1

    const int tid  = threadIdx.x;
    const int w    = tid >> 5;
    const int lane = tid & 31;
    const int cta  = blockIdx.x;

    for (int i = tid; i < HDIM; i += NT) {
        h0s[0][i] = 0.0f; h0s[1][i] = 0.0f;
        h1s[0][i] = 0.0f; h1s[1][i] = 0.0f;
    }
    if (tid == 0) {
        // Read tag bases from OWN CTA's words before posting anything (no race
        // with other CTAs: they only write their own words).
        sbase[0] = (u32t)(ldrel(&g_P0[0][4 * cta]) >> 32);
        sbase[1] = (u32t)(ldrel(&g_P0[1][4 * cta]) >> 32);
        sbase[2] = (u32t)(ldrel(&g_P1[0][4 * cta]) >> 32);
        sbase[3] = (u32t)(ldrel(&g_P1[1][4 * cta]) >> 32);
    }
    __syncthreads();

    if (w < 4) {
        // ================= layer 0: warp w owns hidden unit 4*cta + w ========
        float whh0r[4][16];
        #pragma unroll
        for (int g = 0; g < 4; g++) {
            const float* p = Whh0 + (size_t)(g * HDIM + 4 * cta + w) * HDIM + lane;
            #pragma unroll
            for (int m = 0; m < 16; m++) whh0r[g][m] = p[32 * m];
        }
        float wx[4][3], bz[4];
        if (lane == 0) {
            #pragma unroll
            for (int g = 0; g < 4; g++) {
                int row = g * HDIM + 4 * cta + w;
                wx[g][0] = Wih0[row * 3];
                wx[g][1] = Wih0[row * 3 + 1];
                wx[g][2] = Wih0[row * 3 + 2];
                bz[g] = bih0[row] + bhh0[row];
            }
        }
        float c0 = 0.0f;
        float a0 = 0.f, a1 = 0.f, a2 = 0.f, a3 = 0.f;  // whh0 @ h0(t-1) partials
        const int k = tid;  // 0..127

        for (int t = 0; t < TSTEPS; t++) {
            const int par = t & 1;
            const u32t tg0 = sbase[par]     + (u32t)(t >> 1) + 1u;
            const u32t tg1 = sbase[2 + par] + (u32t)(t >> 1) + 1u;
            // reduce gate partials (overlaps with other-group work)
            #pragma unroll
            for (int off = 16; off; off >>= 1) {
                a0 += __shfl_xor_sync(0xffffffffu, a0, off);
                a1 += __shfl_xor_sync(0xffffffffu, a1, off);
                a2 += __shfl_xor_sync(0xffffffffu, a2, off);
                a3 += __shfl_xor_sync(0xffffffffu, a3, off);
            }
            if (t > 0) BARS(1, 224);        // wait x(t) = pts[t-1] from proj warps
            if (lane == 0) {
                float x0 = 0.f, x1 = 0.f, x2 = 0.f;
                if (t > 0) { x0 = pts[3 * t - 3]; x1 = pts[3 * t - 2]; x2 = pts[3 * t - 1]; }
                float zi = a0 + bz[0] + wx[0][0] * x0 + wx[0][1] * x1 + wx[0][2] * x2;
                float zf = a1 + bz[1] + wx[1][0] * x0 + wx[1][1] * x1 + wx[1][2] * x2;
                float zg = a2 + bz[2] + wx[2][0] * x0 + wx[2][1] * x1 + wx[2][2] * x2;
                float zo = a3 + bz[3] + wx[3][0] * x0 + wx[3][1] * x1 + wx[3][2] * x2;
                c0 = sigm(zf) * c0 + sigm(zi) * tanh_(zg);
                post64(&g_P0[par][4 * cta + w], tg0, sigm(zo) * tanh_(c0));
            }
            // poll h1(t) (hidden under layer-1 compute time) -> smem
            poll4(g_P1[par], k, tg1, h1s[par]);
            BARS(3, 256);                   // h1s[par] + h0s[par] visible to all
            // precompute whh0 @ h0(t) for next step (overlaps with projection)
            a0 = a1 = a2 = a3 = 0.0f;
            const float* hs = h0s[par];
            #pragma unroll
            for (int m = 0; m < 16; m++) {
                float h = hs[lane + 32 * m];
                a0 += whh0r[0][m] * h;
                a1 += whh0r[1][m] * h;
                a2 += whh0r[2][m] * h;
                a3 += whh0r[3][m] * h;
            }
        }
    } else {
        // ====== layer 1: warp 4+u owns unit 4*cta+u; warps 4-6 also project ==
        const int u = w - 4;
        float wih1r[4][16], whh1r[4][16];
        #pragma unroll
        for (int g = 0; g < 4; g++) {
            const float* p1 = Wih1 + (size_t)(g * HDIM + 4 * cta + u) * HDIM + lane;
            const float* p2 = Whh1 + (size_t)(g * HDIM + 4 * cta + u) * HDIM + lane;
            #pragma unroll
            for (int m = 0; m < 16; m++) { wih1r[g][m] = p1[32 * m]; whh1r[g][m] = p2[32 * m]; }
        }
        float wpcr[16];
        float bpcv = 0.0f;
        if (u < 3) {
            const float* p = Wpc + (size_t)u * HDIM + lane;
            #pragma unroll
            for (int m = 0; m < 16; m++) wpcr[m] = p[32 * m];
            if (lane == 0) bpcv = bpc[u];
        }
        float bz[4];
        if (lane == 0) {
            #pragma unroll
            for (int g = 0; g < 4; g++) {
                int row = g * HDIM + 4 * cta + u;
                bz[g] = bih1[row] + bhh1[row];
            }
        }
        float c1 = 0.0f;
        const int k = tid - 128;  // 0..127

        for (int t = 0; t < TSTEPS; t++) {
            const int par = t & 1;
            const u32t tg0 = sbase[par]     + (u32t)(t >> 1) + 1u;
            const u32t tg1 = sbase[2 + par] + (u32t)(t >> 1) + 1u;
            // poll h0(t) (hidden under layer-0 compute time) -> smem
            poll4(g_P0[par], k, tg0, h0s[par]);
            BARS(2, 128);                   // h0s[par] complete within group
            float a0 = 0.f, a1 = 0.f, a2 = 0.f, a3 = 0.f;
            const float* hn = h0s[par];
            const float* hp = h1s[par ^ 1]; // h1(t-1); zeros at t=0
            #pragma unroll
            for (int m = 0; m < 16; m++) {
                float x = hn[lane + 32 * m];
                float y = hp[lane + 32 * m];
                a0 += wih1r[0][m] * x + whh1r[0][m] * y;
                a1 += wih1r[1][m] * x + whh1r[1][m] * y;
                a2 += wih1r[2][m] * x + whh1r[2][m] * y;
                a3 += wih1r[3][m] * x + whh1r[3][m] * y;
            }
            #pragma unroll
            for (int off = 16; off; off >>= 1) {
                a0 += __shfl_xor_sync(0xffffffffu, a0, off);
                a1 += __shfl_xor_sync(0xffffffffu, a1, off);
                a2 += __shfl_xor_sync(0xffffffffu, a2, off);
                a3 += __shfl_xor_sync(0xffffffffu, a3, off);
            }
            if (lane == 0) {
                float zi = a0 + bz[0];
                float zf = a1 + bz[1];
                float zg = a2 + bz[2];
                float zo = a3 + bz[3];
                c1 = sigm(zf) * c1 + sigm(zi) * tanh_(zg);
                post64(&g_P1[par][4 * cta + u], tg1, sigm(zo) * tanh_(c1));
            }
            BARS(3, 256);                   // join with layer-0 pollers of h1(t)
            if (u < 3) {
                // projection component u: point(t)[u] = Wpc[u] . h1(t) + bpc[u]
                float s = 0.0f;
                const float* h1p = h1s[par];
                #pragma unroll
                for (int m = 0; m < 16; m++) s += wpcr[m] * h1p[lane + 32 * m];
                #pragma unroll
                for (int off = 16; off; off >>= 1) s += __shfl_xor_sync(0xffffffffu, s, off);
                if (lane == 0) pts[3 * t + u] = s + bpcv;
                if (t < TSTEPS - 1) BARS(1, 224);   // release layer-0 for x(t+1)
            }
        }
    }
    __syncthreads();

    // ---- masked broadcast: out[row][t][j] = (t < seq[row]) ? pts[t][j] : 0 --
    const int row0 = cta * BROWS;
    for (int idx = tid; idx < BROWS * 63; idx += NT) {
        int rl = idx / 63;
        int q  = idx - 63 * rl;
        int row = row0 + rl;
        int L = seq[row];
        int e = 4 * q;
        float4 v;
        v.x = ((e    ) / 3 < L) ? pts[e    ] : 0.0f;
        v.y = ((e + 1) / 3 < L) ? pts[e + 1] : 0.0f;
        v.z = ((e + 2) / 3 < L) ? pts[e + 2] : 0.0f;
        v.w = ((e + 3) / 3 < L) ? pts[e + 3] : 0.0f;
        reinterpret_cast<float4*>(out)[(size_t)row * 63 + q] = v;
    }
}

extern "C" void kernel_launch(void* const* d_in, const int* in_sizes, int n_in,
                              void* d_out, int out_size)
{
    // 0 features (unused), 1 seq_lengths, 2 W_ih0, 3 W_hh0, 4 b_ih0, 5 b_hh0,
    // 6 W_ih1, 7 W_hh1, 8 b_ih1, 9 b_hh1, 10 W_pc, 11 b_pc
    (void)in_sizes; (void)n_in; (void)out_size;
    lstm_persistent_kernel<<<NCTA, NT>>>(
        (const int*)  d_in[1],
        (const float*)d_in[2], (const float*)d_in[3],
        (const float*)d_in[4], (const float*)d_in[5],
        (const float*)d_in[6], (const float*)d_in[7],
        (const float*)d_in[8], (const float*)d_in[9],
        (const float*)d_in[10], (const float*)d_in[11],
        (float*)d_out);
}

// round 4
// speedup vs baseline: 1.2661x; 1.2187x over previous
#include <cuda_runtime.h>
#include <cstdint>

// DecoderLSTM on B200: batch dimension is degenerate (features unused, x0=0,
// shared weights) -> ONE 84-step 2-layer LSTM (H=512) computed cooperatively
// by 128 persistent CTAs. Exchanges use tagged 64-bit words (tag|payload in
// one 8B atomic word) REPLICATED 8x across separate L2 lines so the 128-CTA
// broadcast doesn't serialize on a few LTS slices. Finally points[84][3] is
// broadcast into out[16384][84][3] masked by seq_lengths.

#define NCTA   128
#define NT     256
#define HDIM   512
#define TSTEPS 84
#define BROWS  128     // batch rows per CTA
#define NREP   8       // post replication factor

typedef unsigned long long u64t;
typedef unsigned int u32t;

// Tagged posts: upper 32 = monotonic version tag, lower 32 = float bits.
// 8B-aligned relaxed accesses are single-copy atomic -> tag+payload travel
// together. Never reset: each run reads its own CTA's words at entry as the
// tag base (equal across runs/replicas by construction) -> graph replays are
// deterministic. Replica r is a separate 4KB array so different replicas hit
// different L2 slice sets.
__device__ u64t g_P0[NREP][2][HDIM];   // layer-0 h posts
__device__ u64t g_P1[NREP][2][HDIM];   // layer-1 h posts

static __device__ __forceinline__ void post64(u64t* p, u32t tag, float h) {
    u64t v = ((u64t)tag << 32) | (u64t)__float_as_uint(h);
    asm volatile("st.relaxed.gpu.global.u64 [%0], %1;" :: "l"(p), "l"(v) : "memory");
}
static __device__ __forceinline__ u64t ldrel(const u64t* p) {
    u64t v;
    asm volatile("ld.relaxed.gpu.global.u64 %0, [%1];" : "=l"(v) : "l"(p) : "memory");
    return v;
}
__device__ __forceinline__ float sigm(float z)  { return 1.0f / (1.0f + __expf(-z)); }
__device__ __forceinline__ float tanh_(float z) { return 2.0f / (1.0f + __expf(-2.0f * z)) - 1.0f; }

#define BARS(id, n) asm volatile("bar.sync %0, %1;" :: "r"(id), "r"(n) : "memory")

// Poll 4 tagged words (warp-coalesced stride-128 layout), stage floats to smem.
static __device__ __forceinline__ void poll4(const u64t* arr, int k, u32t tag, float* dst) {
    u64t v0 = ldrel(arr + k);
    u64t v1 = ldrel(arr + k + 128);
    u64t v2 = ldrel(arr + k + 256);
    u64t v3 = ldrel(arr + k + 384);
    while ((u32t)(v0 >> 32) != tag) v0 = ldrel(arr + k);
    while ((u32t)(v1 >> 32) != tag) v1 = ldrel(arr + k + 128);
    while ((u32t)(v2 >> 32) != tag) v2 = ldrel(arr + k + 256);
    while ((u32t)(v3 >> 32) != tag) v3 = ldrel(arr + k + 384);
    dst[k]       = __uint_as_float((u32t)v0);
    dst[k + 128] = __uint_as_float((u32t)v1);
    dst[k + 256] = __uint_as_float((u32t)v2);
    dst[k + 384] = __uint_as_float((u32t)v3);
}

__global__ void __launch_bounds__(NT, 1)
lstm_persistent_kernel(const int* __restrict__ seq,
                       const float* __restrict__ Wih0, const float* __restrict__ Whh0,
                       const float* __restrict__ bih0, const float* __restrict__ bhh0,
                       const float* __restrict__ Wih1, const float* __restrict__ Whh1,
                       const float* __restrict__ bih1, const float* __restrict__ bhh1,
                       const float* __restrict__ Wpc,  const float* __restrict__ bpc,
                       float* __restrict__ out)
{
    __shared__ float h0s[2][HDIM];
    __shared__ float h1s[2][HDIM];
    __shared__ float pts[TSTEPS * 3];
    __shared__ u32t  sbase[4];      // tag bases: P0 par0/par1, P1 par0/par1

    const int tid  = threadIdx.x;
    const int w    = tid >> 5;
    const int lane = tid & 31;
    const int cta  = blockIdx.x;
    const int rep  = cta & (NREP - 1);   // which replica this CTA polls

    for (int i = tid; i < HDIM; i += NT) {
        h0s[0][i] = 0.0f; h0s[1][i] = 0.0f;
        h1s[0][i] = 0.0f; h1s[1][i] = 0.0f;
    }
    if (tid == 0) {
        // Read tag bases from OWN CTA's words (replica 0) before posting
        // anything; no race (other CTAs never write these words).
        sbase[0] = (u32t)(ldrel(&g_P0[0][0][4 * cta]) >> 32);
        sbase[1] = (u32t)(ldrel(&g_P0[0][1][4 * cta]) >> 32);
        sbase[2] = (u32t)(ldrel(&g_P1[0][0][4 * cta]) >> 32);
        sbase[3] = (u32t)(ldrel(&g_P1[0][1][4 * cta]) >> 32);
    }
    __syncthreads();

    if (w < 4) {
        // ================= layer 0: warp w owns hidden unit 4*cta + w ========
        float whh0r[4][16];
        #pragma unroll
        for (int g = 0; g < 4; g++) {
            const float* p = Whh0 + (size_t)(g * HDIM + 4 * cta + w) * HDIM + lane;
            #pragma unroll
            for (int m = 0; m < 16; m++) whh0r[g][m] = p[32 * m];
        }
        float wx[4][3], bz[4];
        if (lane == 0) {
            #pragma unroll
            for (int g = 0; g < 4; g++) {
                int row = g * HDIM + 4 * cta + w;
                wx[g][0] = Wih0[row * 3];
                wx[g][1] = Wih0[row * 3 + 1];
                wx[g][2] = Wih0[row * 3 + 2];
                bz[g] = bih0[row] + bhh0[row];
            }
        }
        float c0 = 0.0f;
        float a0 = 0.f, a1 = 0.f, a2 = 0.f, a3 = 0.f;  // whh0 @ h0(t-1) partials
        const int k = tid;  // 0..127

        for (int t = 0; t < TSTEPS; t++) {
            const int par = t & 1;
            const u32t tg0 = sbase[par]     + (u32t)(t >> 1) + 1u;
            const u32t tg1 = sbase[2 + par] + (u32t)(t >> 1) + 1u;
            // reduce gate partials
            #pragma unroll
            for (int off = 16; off; off >>= 1) {
                a0 += __shfl_xor_sync(0xffffffffu, a0, off);
                a1 += __shfl_xor_sync(0xffffffffu, a1, off);
                a2 += __shfl_xor_sync(0xffffffffu, a2, off);
                a3 += __shfl_xor_sync(0xffffffffu, a3, off);
            }
            if (t > 0) BARS(1, 224);        // wait x(t) = pts[t-1] from proj warps
            float hval = 0.0f;
            if (lane == 0) {
                float x0 = 0.f, x1 = 0.f, x2 = 0.f;
                if (t > 0) { x0 = pts[3 * t - 3]; x1 = pts[3 * t - 2]; x2 = pts[3 * t - 1]; }
                float zi = a0 + bz[0] + wx[0][0] * x0 + wx[0][1] * x1 + wx[0][2] * x2;
                float zf = a1 + bz[1] + wx[1][0] * x0 + wx[1][1] * x1 + wx[1][2] * x2;
                float zg = a2 + bz[2] + wx[2][0] * x0 + wx[2][1] * x1 + wx[2][2] * x2;
                float zo = a3 + bz[3] + wx[3][0] * x0 + wx[3][1] * x1 + wx[3][2] * x2;
                c0 = sigm(zf) * c0 + sigm(zi) * tanh_(zg);
                hval = sigm(zo) * tanh_(c0);
            }
            hval = __shfl_sync(0xffffffffu, hval, 0);
            if (lane < NREP)                 // post to all replicas in parallel
                post64(&g_P0[lane][par][4 * cta + w], tg0, hval);
            // poll h1(t) from this CTA's replica (hidden under layer-1 compute)
            poll4(g_P1[rep][par], k, tg1, h1s[par]);
            BARS(3, 256);                   // h1s[par] + h0s[par] visible to all
            // precompute whh0 @ h0(t) for next step (overlaps with projection)
            a0 = a1 = a2 = a3 = 0.0f;
            const float* hs = h0s[par];
            #pragma unroll
            for (int m = 0; m < 16; m++) {
                float h = hs[lane + 32 * m];
                a0 += whh0r[0][m] * h;
                a1 += whh0r[1][m] * h;
                a2 += whh0r[2][m] * h;
                a3 += whh0r[3][m] * h;
            }
        }
    } else {
        // ====== layer 1: warp 4+u owns unit 4*cta+u; warps 4-6 also project ==
        const int u = w - 4;
        float wih1r[4][16], whh1r[4][16];
        #pragma unroll
        for (int g = 0; g < 4; g++) {
            const float* p1 = Wih1 + (size_t)(g * HDIM + 4 * cta + u) * HDIM + lane;
            const float* p2 = Whh1 + (size_t)(g * HDIM + 4 * cta + u) * HDIM + lane;
            #pragma unroll
            for (int m = 0; m < 16; m++) { wih1r[g][m] = p1[32 * m]; whh1r[g][m] = p2[32 * m]; }
        }
        float wpcr[16];
        float bpcv = 0.0f;
        if (u < 3) {
            const float* p = Wpc + (size_t)u * HDIM + lane;
            #pragma unroll
            for (int m = 0; m < 16; m++) wpcr[m] = p[32 * m];
            if (lane == 0) bpcv = bpc[u];
        }
        float bz[4];
        if (lane == 0) {
            #pragma unroll
            for (int g = 0; g < 4; g++) {
                int row = g * HDIM + 4 * cta + u;
                bz[g] = bih1[row] + bhh1[row];
            }
        }
        float c1 = 0.0f;
        const int k = tid - 128;  // 0..127

        for (int t = 0; t < TSTEPS; t++) {
            const int par = t & 1;
            const u32t tg0 = sbase[par]     + (u32t)(t >> 1) + 1u;
            const u32t tg1 = sbase[2 + par] + (u32t)(t >> 1) + 1u;
            // poll h0(t) from this CTA's replica (hidden under layer-0 compute)
            poll4(g_P0[rep][par], k, tg0, h0s[par]);
            BARS(2, 128);                   // h0s[par] complete within group
            float a0 = 0.f, a1 = 0.f, a2 = 0.f, a3 = 0.f;
            const float* hn = h0s[par];
            const float* hp = h1s[par ^ 1]; // h1(t-1); zeros at t=0
            #pragma unroll
            for (int m = 0; m < 16; m++) {
                float x = hn[lane + 32 * m];
                float y = hp[lane + 32 * m];
                a0 += wih1r[0][m] * x + whh1r[0][m] * y;
                a1 += wih1r[1][m] * x + whh1r[1][m] * y;
                a2 += wih1r[2][m] * x + whh1r[2][m] * y;
                a3 += wih1r[3][m] * x + whh1r[3][m] * y;
            }
            #pragma unroll
            for (int off = 16; off; off >>= 1) {
                a0 += __shfl_xor_sync(0xffffffffu, a0, off);
                a1 += __shfl_xor_sync(0xffffffffu, a1, off);
                a2 += __shfl_xor_sync(0xffffffffu, a2, off);
                a3 += __shfl_xor_sync(0xffffffffu, a3, off);
            }
            float hval = 0.0f;
            if (lane == 0) {
                float zi = a0 + bz[0];
                float zf = a1 + bz[1];
                float zg = a2 + bz[2];
                float zo = a3 + bz[3];
                c1 = sigm(zf) * c1 + sigm(zi) * tanh_(zg);
                hval = sigm(zo) * tanh_(c1);
            }
            hval = __shfl_sync(0xffffffffu, hval, 0);
            if (lane < NREP)
                post64(&g_P1[lane][par][4 * cta + u], tg1, hval);
            BARS(3, 256);                   // join with layer-0 pollers of h1(t)
            if (u < 3) {
                // projection component u: point(t)[u] = Wpc[u] . h1(t) + bpc[u]
                float s = 0.0f;
                const float* h1p = h1s[par];
                #pragma unroll
                for (int m = 0; m < 16; m++) s += wpcr[m] * h1p[lane + 32 * m];
                #pragma unroll
                for (int off = 16; off; off >>= 1) s += __shfl_xor_sync(0xffffffffu, s, off);
                if (lane == 0) pts[3 * t + u] = s + bpcv;
                if (t < TSTEPS - 1) BARS(1, 224);   // release layer-0 for x(t+1)
            }
        }
    }
    __syncthreads();

    // ---- masked broadcast: out[row][t][j] = (t < seq[row]) ? pts[t][j] : 0 --
    const int row0 = cta * BROWS;
    for (int idx = tid; idx < BROWS * 63; idx += NT) {
        int rl = idx / 63;
        int q  = idx - 63 * rl;
        int row = row0 + rl;
        int L = seq[row];
        int e = 4 * q;
        float4 v;
        v.x = ((e    ) / 3 < L) ? pts[e    ] : 0.0f;
        v.y = ((e + 1) / 3 < L) ? pts[e + 1] : 0.0f;
        v.z = ((e + 2) / 3 < L) ? pts[e + 2] : 0.0f;
        v.w = ((e + 3) / 3 < L) ? pts[e + 3] : 0.0f;
        reinterpret_cast<float4*>(out)[(size_t)row * 63 + q] = v;
    }
}

extern "C" void kernel_launch(void* const* d_in, const int* in_sizes, int n_in,
                              void* d_out, int out_size)
{
    // 0 features (unused), 1 seq_lengths, 2 W_ih0, 3 W_hh0, 4 b_ih0, 5 b_hh0,
    // 6 W_ih1, 7 W_hh1, 8 b_ih1, 9 b_hh1, 10 W_pc, 11 b_pc
    (void)in_sizes; (void)n_in; (void)out_size;
    lstm_persistent_kernel<<<NCTA, NT>>>(
        (const int*)  d_in[1],
        (const float*)d_in[2], (const float*)d_in[3],
        (const float*)d_in[4], (const float*)d_in[5],
        (const float*)d_in[6], (const float*)d_in[7],
        (const float*)d_in[8], (const float*)d_in[9],
        (const float*)d_in[10], (const float*)d_in[11],
        (float*)d_out);
}